// round 11
// baseline (speedup 1.0000x reference)
#include <cuda_runtime.h>
#include <cstddef>

// Problem constants (match reference_code)
#define NU 500000
#define NP 100000
#define DIMF 64
#define UF (NU * DIMF)   // 32,000,000 floats (128 MB)
#define PF (NP * DIMF)   //  6,400,000 floats (25.6 MB)
#define NE 1250000       // edges per list

// ---------------------------------------------------------------------------
// Scratch (__device__ globals — allocation-guard-safe). ~481 MB total.
// ---------------------------------------------------------------------------
__device__ float g_au0[UF];
__device__ float g_au1[UF];
__device__ float g_au2[UF];
__device__ float g_ap0[PF];
__device__ float g_ap1[PF];
__device__ float g_ap2[PF];

__device__ int   g_deg_er[NU], g_deg_ew[NU], g_deg_rr[NP], g_deg_rw[NP];
__device__ int   g_off_er[NU], g_off_ew[NU], g_off_rr[NP], g_off_rw[NP];
__device__ int   g_cur_er[NU], g_cur_ew[NU], g_cur_rr[NP], g_cur_rw[NP];
__device__ float g_scl_er[NU], g_scl_ew[NU], g_scl_rr[NP], g_scl_rw[NP];
__device__ int   g_csr_er[NE], g_csr_ew[NE], g_csr_rr[NE], g_csr_rw[NE];

// ---------------------------------------------------------------------------
// Setup kernels
// ---------------------------------------------------------------------------
__global__ void k_zero_deg(int* __restrict__ du0, int* __restrict__ du1,
                           int* __restrict__ dp0, int* __restrict__ dp1) {
    int i = blockIdx.x * blockDim.x + threadIdx.x;
    if (i < NU) { du0[i] = 0; du1[i] = 0; }
    if (i < NP) { dp0[i] = 0; dp1[i] = 0; }
}

__global__ void k_deg4(const int* __restrict__ er, const int* __restrict__ ew,
                       const int* __restrict__ rr, const int* __restrict__ rw, int E,
                       int* __restrict__ der, int* __restrict__ dew,
                       int* __restrict__ drr, int* __restrict__ drw) {
    int i = blockIdx.x * blockDim.x + threadIdx.x;
    if (i >= E) return;
    atomicAdd(&der[er[i]], 1);
    atomicAdd(&dew[ew[i]], 1);
    atomicAdd(&drr[rr[i]], 1);
    atomicAdd(&drw[rw[i]], 1);
}

// Four exclusive prefix-sums, one block each. off[] and cur[] both get the
// exclusive prefix (cur is the binning cursor).
__global__ void __launch_bounds__(1024)
k_scan4(const int* d0, int n0, int* o0, int* c0,
        const int* d1, int n1, int* o1, int* c1,
        const int* d2, int n2, int* o2, int* c2,
        const int* d3, int n3, int* o3, int* c3) {
    const int* deg; int n; int* off; int* cur;
    if      (blockIdx.x == 0) { deg = d0; n = n0; off = o0; cur = c0; }
    else if (blockIdx.x == 1) { deg = d1; n = n1; off = o1; cur = c1; }
    else if (blockIdx.x == 2) { deg = d2; n = n2; off = o2; cur = c2; }
    else                      { deg = d3; n = n3; off = o3; cur = c3; }

    __shared__ int sh[1024];
    int t = threadIdx.x;
    int C = (n + 1023) >> 10;
    int lo = t * C;
    int hi = lo + C; if (hi > n) hi = n;
    if (lo > n) lo = n;

    int sum = 0;
    for (int i = lo; i < hi; i++) sum += deg[i];
    sh[t] = sum;
    __syncthreads();
    // inclusive Hillis-Steele scan over 1024 partials
    for (int ofs = 1; ofs < 1024; ofs <<= 1) {
        int v = (t >= ofs) ? sh[t - ofs] : 0;
        __syncthreads();
        sh[t] += v;
        __syncthreads();
    }
    int run = sh[t] - sum;   // exclusive prefix for this chunk
    for (int i = lo; i < hi; i++) {
        off[i] = run; cur[i] = run;
        run += deg[i];
    }
}

// Bin all four edge lists: csr[pos] = dst, pos = cursor[src]++.
__global__ void k_bin4(const int* __restrict__ er, const int* __restrict__ ew,
                       const int* __restrict__ rr, const int* __restrict__ rw, int E,
                       int* __restrict__ cer, int* __restrict__ cew,
                       int* __restrict__ crr, int* __restrict__ crw,
                       int* __restrict__ xer, int* __restrict__ xew,
                       int* __restrict__ xrr, int* __restrict__ xrw) {
    int i = blockIdx.x * blockDim.x + threadIdx.x;
    if (i >= E) return;
    { int s = er[i], d = er[E + i]; xer[atomicAdd(&cer[s], 1)] = d; }
    { int s = ew[i], d = ew[E + i]; xew[atomicAdd(&cew[s], 1)] = d; }
    { int s = rr[i], d = rr[E + i]; xrr[atomicAdd(&crr[s], 1)] = d; }
    { int s = rw[i], d = rw[E + i]; xrw[atomicAdd(&crw[s], 1)] = d; }
}

// scale = 0.5 / max(deg, 1): folds degree-normalization AND the (r+w)/2 avg.
__global__ void k_scale2(const int* __restrict__ da, float* __restrict__ sa,
                         const int* __restrict__ db, float* __restrict__ sb, int n) {
    int i = blockIdx.x * blockDim.x + threadIdx.x;
    if (i < n) {
        int a = da[i], b = db[i];
        sa[i] = 0.5f / (float)(a > 1 ? a : 1);
        sb[i] = 0.5f / (float)(b > 1 ? b : 1);
    }
}

// ---------------------------------------------------------------------------
// Gather-side propagation: 16 lanes per destination node.
//   out[n] = scl1[n] * sum_{j in csr1[n]} feat[j]  +  scl2[n] * sum_{csr2[n]}
// Each 16-lane group preloads up to 16 edge indices coalesced, broadcasts via
// half-warp shfl. All 16 lanes of a group share n -> identical trip counts ->
// every shfl is convergent within its half-warp mask. Writes each output row
// exactly once: no zeroing, no atomics.
// ---------------------------------------------------------------------------
__global__ void __launch_bounds__(256, 8)
k_gather2(const int* __restrict__ off1, const int* __restrict__ deg1,
          const int* __restrict__ csr1, const float* __restrict__ scl1,
          const int* __restrict__ off2, const int* __restrict__ deg2,
          const int* __restrict__ csr2, const float* __restrict__ scl2,
          int N, const float4* __restrict__ feat, float4* __restrict__ out) {
    int t = blockIdx.x * blockDim.x + threadIdx.x;
    if (t >= N * 16) return;    // N*16 is a multiple of 256: never splits a warp
    int n    = t >> 4;
    int lane = t & 15;
    unsigned hmask = 0xFFFFu << (threadIdx.x & 16);   // own half-warp only

    float4 a1 = make_float4(0.f, 0.f, 0.f, 0.f);
    {
        const int* p = csr1 + __ldg(off1 + n);
        int d = __ldg(deg1 + n);
        for (int base = 0; base < d; base += 16) {
            int m = d - base; if (m > 16) m = 16;
            int my = (lane < m) ? __ldg(p + base + lane) : 0;
            for (int j = 0; j < m; j++) {
                int idx = __shfl_sync(hmask, my, j, 16);
                float4 v = __ldg(feat + (size_t)idx * 16 + lane);
                a1.x += v.x; a1.y += v.y; a1.z += v.z; a1.w += v.w;
            }
        }
    }
    float4 a2 = make_float4(0.f, 0.f, 0.f, 0.f);
    {
        const int* p = csr2 + __ldg(off2 + n);
        int d = __ldg(deg2 + n);
        for (int base = 0; base < d; base += 16) {
            int m = d - base; if (m > 16) m = 16;
            int my = (lane < m) ? __ldg(p + base + lane) : 0;
            for (int j = 0; j < m; j++) {
                int idx = __shfl_sync(hmask, my, j, 16);
                float4 v = __ldg(feat + (size_t)idx * 16 + lane);
                a2.x += v.x; a2.y += v.y; a2.z += v.z; a2.w += v.w;
            }
        }
    }
    float s1 = __ldg(scl1 + n), s2 = __ldg(scl2 + n);
    float4 o;
    o.x = a1.x * s1 + a2.x * s2;
    o.y = a1.y * s1 + a2.y * s2;
    o.z = a1.z * s1 + a2.z * s2;
    o.w = a1.w * s1 + a2.w * s2;
    out[(size_t)n * 16 + lane] = o;
}

// out = 0.25 * (base + l1 + l2 + l3)   (mean over the 4 layer snapshots)
__global__ void k_final3(const float4* __restrict__ base,
                         const float4* __restrict__ a,
                         const float4* __restrict__ b,
                         const float4* __restrict__ c,
                         float4* __restrict__ out, int n4) {
    int i = blockIdx.x * blockDim.x + threadIdx.x;
    if (i < n4) {
        float4 x = base[i], p = a[i], q = b[i], r = c[i];
        x.x = 0.25f * (x.x + p.x + q.x + r.x);
        x.y = 0.25f * (x.y + p.y + q.y + r.y);
        x.z = 0.25f * (x.z + p.z + q.z + r.z);
        x.w = 0.25f * (x.w + p.w + q.w + r.w);
        out[i] = x;
    }
}

// ---------------------------------------------------------------------------
// Launch (no statics, no caching — harness contract)
// ---------------------------------------------------------------------------
static inline int nblk(long long n, int t) { return (int)((n + t - 1) / t); }

extern "C" void kernel_launch(void* const* d_in, const int* in_sizes, int n_in,
                              void* d_out, int out_size) {
    const float* user_emb  = (const float*)d_in[0];
    const float* paper_emb = (const float*)d_in[1];
    const int*   er        = (const int*)d_in[2];
    const int*   ew        = (const int*)d_in[3];
    const int*   rr        = (const int*)d_in[4];
    const int*   rw        = (const int*)d_in[5];
    const int E = in_sizes[2] / 2;

    float* out = (float*)d_out;

    float *au[3], *ap[3];
    int *deg_er, *deg_ew, *deg_rr, *deg_rw;
    int *off_er, *off_ew, *off_rr, *off_rw;
    int *cur_er, *cur_ew, *cur_rr, *cur_rw;
    int *csr_er, *csr_ew, *csr_rr, *csr_rw;
    float *scl_er, *scl_ew, *scl_rr, *scl_rw;
    cudaGetSymbolAddress((void**)&au[0], g_au0);
    cudaGetSymbolAddress((void**)&au[1], g_au1);
    cudaGetSymbolAddress((void**)&au[2], g_au2);
    cudaGetSymbolAddress((void**)&ap[0], g_ap0);
    cudaGetSymbolAddress((void**)&ap[1], g_ap1);
    cudaGetSymbolAddress((void**)&ap[2], g_ap2);
    cudaGetSymbolAddress((void**)&deg_er, g_deg_er);
    cudaGetSymbolAddress((void**)&deg_ew, g_deg_ew);
    cudaGetSymbolAddress((void**)&deg_rr, g_deg_rr);
    cudaGetSymbolAddress((void**)&deg_rw, g_deg_rw);
    cudaGetSymbolAddress((void**)&off_er, g_off_er);
    cudaGetSymbolAddress((void**)&off_ew, g_off_ew);
    cudaGetSymbolAddress((void**)&off_rr, g_off_rr);
    cudaGetSymbolAddress((void**)&off_rw, g_off_rw);
    cudaGetSymbolAddress((void**)&cur_er, g_cur_er);
    cudaGetSymbolAddress((void**)&cur_ew, g_cur_ew);
    cudaGetSymbolAddress((void**)&cur_rr, g_cur_rr);
    cudaGetSymbolAddress((void**)&cur_rw, g_cur_rw);
    cudaGetSymbolAddress((void**)&csr_er, g_csr_er);
    cudaGetSymbolAddress((void**)&csr_ew, g_csr_ew);
    cudaGetSymbolAddress((void**)&csr_rr, g_csr_rr);
    cudaGetSymbolAddress((void**)&csr_rw, g_csr_rw);
    cudaGetSymbolAddress((void**)&scl_er, g_scl_er);
    cudaGetSymbolAddress((void**)&scl_ew, g_scl_ew);
    cudaGetSymbolAddress((void**)&scl_rr, g_scl_rr);
    cudaGetSymbolAddress((void**)&scl_rw, g_scl_rw);

    const int T = 256;
    const int UF4 = UF / 4, PF4 = PF / 4;
    const int GU = nblk((long long)NU * 16, T);   // user-gather grid
    const int GP = nblk((long long)NP * 16, T);   // paper-gather grid

    // 1) degrees (launches 1-2)
    k_zero_deg<<<nblk(NU, T), T>>>(deg_er, deg_ew, deg_rr, deg_rw);
    k_deg4<<<nblk(E, T), T>>>(er, ew, rr, rw, E, deg_er, deg_ew, deg_rr, deg_rw);

    // 2) CSR build: scan (3) + bin (4)
    k_scan4<<<4, 1024>>>(deg_er, NU, off_er, cur_er,
                         deg_ew, NU, off_ew, cur_ew,
                         deg_rr, NP, off_rr, cur_rr,
                         deg_rw, NP, off_rw, cur_rw);
    k_bin4<<<nblk(E, T), T>>>(er, ew, rr, rw, E,
                              cur_er, cur_ew, cur_rr, cur_rw,
                              csr_er, csr_ew, csr_rr, csr_rw);

    // 3) user scales (5), then first user gather at launch index 6 (ncu -s 5)
    k_scale2<<<nblk(NU, T), T>>>(deg_er, scl_er, deg_ew, scl_ew, NU);
    k_gather2<<<GU, T>>>(off_er, deg_er, csr_er, scl_er,
                         off_ew, deg_ew, csr_ew, scl_ew,
                         NU, (const float4*)paper_emb, (float4*)au[0]);

    // paper scales (7), paper gather L0 (8)
    k_scale2<<<nblk(NP, T), T>>>(deg_rr, scl_rr, deg_rw, scl_rw, NP);
    k_gather2<<<GP, T>>>(off_rr, deg_rr, csr_rr, scl_rr,
                         off_rw, deg_rw, csr_rw, scl_rw,
                         NP, (const float4*)au[0], (float4*)ap[0]);

    // layers 1..2
    for (int L = 1; L < 3; L++) {
        k_gather2<<<GU, T>>>(off_er, deg_er, csr_er, scl_er,
                             off_ew, deg_ew, csr_ew, scl_ew,
                             NU, (const float4*)ap[L - 1], (float4*)au[L]);
        k_gather2<<<GP, T>>>(off_rr, deg_rr, csr_rr, scl_rr,
                             off_rw, deg_rw, csr_rw, scl_rw,
                             NP, (const float4*)au[L], (float4*)ap[L]);
    }

    // 4) finalize: mean over {layer-0 emb, L1, L2, L3}; out = [u_final | p_final]
    k_final3<<<nblk(UF4, T), T>>>((const float4*)user_emb,
                                  (const float4*)au[0], (const float4*)au[1],
                                  (const float4*)au[2], (float4*)out, UF4);
    k_final3<<<nblk(PF4, T), T>>>((const float4*)paper_emb,
                                  (const float4*)ap[0], (const float4*)ap[1],
                                  (const float4*)ap[2],
                                  (float4*)(out + (size_t)UF), PF4);
}

// round 16
// speedup vs baseline: 1.2432x; 1.2432x over previous
#include <cuda_runtime.h>
#include <cstddef>

// Problem constants (match reference_code)
#define NU 500000
#define NP 100000
#define DIMF 64
#define UF (NU * DIMF)   // 32,000,000 floats (128 MB)
#define PF (NP * DIMF)   //  6,400,000 floats (25.6 MB)

// ---------------------------------------------------------------------------
// Scratch (static device globals — allocation-guard-safe). ~461 MB total.
// ---------------------------------------------------------------------------
__device__ float g_au0[UF];
__device__ float g_au1[UF];
__device__ float g_au2[UF];
__device__ float g_ap0[PF];
__device__ float g_ap1[PF];
__device__ float g_ap2[PF];

__device__ int   g_deg_er[NU], g_deg_ew[NU], g_deg_rr[NP], g_deg_rw[NP];
__device__ float g_scl_er[NU], g_scl_ew[NU], g_scl_rr[NP], g_scl_rw[NP];

// ---------------------------------------------------------------------------
// Vector f32 L2 reduction with scalar fallback.
// ---------------------------------------------------------------------------
__device__ __forceinline__ void red_add_v4(float* dst, float a, float b, float c, float d) {
#if defined(__CUDA_ARCH__) && (__CUDA_ARCH__ >= 900)
    asm volatile("red.global.add.v4.f32 [%0], {%1,%2,%3,%4};"
                 :: "l"(dst), "f"(a), "f"(b), "f"(c), "f"(d) : "memory");
#else
    atomicAdd(dst + 0, a); atomicAdd(dst + 1, b);
    atomicAdd(dst + 2, c); atomicAdd(dst + 3, d);
#endif
}

// ---------------------------------------------------------------------------
// Kernels
// ---------------------------------------------------------------------------
// Opening kernel: zero au0 (float4) AND all four degree arrays in one launch,
// so the first big scatter can sit at launch index 4 (ncu capture slot).
__global__ void k_zero_init(float4* __restrict__ au0,
                            int* __restrict__ du0, int* __restrict__ du1,
                            int* __restrict__ dp0, int* __restrict__ dp1,
                            int n4) {
    int i = blockIdx.x * blockDim.x + threadIdx.x;
    if (i < n4) au0[i] = make_float4(0.f, 0.f, 0.f, 0.f);
    if (i < NU) { du0[i] = 0; du1[i] = 0; }
    if (i < NP) { dp0[i] = 0; dp1[i] = 0; }
}

__global__ void k_zero_f4(float4* __restrict__ p, int n4) {
    int i = blockIdx.x * blockDim.x + threadIdx.x;
    if (i < n4) p[i] = make_float4(0.f, 0.f, 0.f, 0.f);
}

// All four degree histograms in one launch.
__global__ void k_deg4(const int* __restrict__ er, const int* __restrict__ ew,
                       const int* __restrict__ rr, const int* __restrict__ rw, int E,
                       int* __restrict__ der, int* __restrict__ dew,
                       int* __restrict__ drr, int* __restrict__ drw) {
    int i = blockIdx.x * blockDim.x + threadIdx.x;
    if (i >= E) return;
    atomicAdd(&der[er[i]], 1);
    atomicAdd(&dew[ew[i]], 1);
    atomicAdd(&drr[rr[i]], 1);
    atomicAdd(&drw[rw[i]], 1);
}

// scale = 0.5 / max(deg, 1): folds degree-normalization AND the (r+w)/2 avg.
__global__ void k_scale2(const int* __restrict__ da, float* __restrict__ sa,
                         const int* __restrict__ db, float* __restrict__ sb, int n) {
    int i = blockIdx.x * blockDim.x + threadIdx.x;
    if (i < n) {
        int a = da[i], b = db[i];
        sa[i] = 0.5f / (float)(a > 1 ? a : 1);
        sb[i] = 0.5f / (float)(b > 1 ? b : 1);
    }
}

// Fused dual-edge-list scatter:  agg[src] += scale[src] * feat[dst]
// for both edge lists of one phase. 16 threads per edge, one float4 each.
// Grid-stride over 2*E*16 work items; E is a multiple of 16, so the list
// boundary is warp-aligned -> no intra-warp divergence.
__global__ void __launch_bounds__(256, 8)
k_scatter2(const int* __restrict__ e1, const float* __restrict__ scl1,
           const int* __restrict__ e2, const float* __restrict__ scl2,
           int E,
           const float* __restrict__ feat,
           float* __restrict__ agg) {
    const int half  = E * 16;
    const int total = half * 2;
    const int step  = gridDim.x * blockDim.x;
    for (int t = blockIdx.x * blockDim.x + threadIdx.x; t < total; t += step) {
        const int* edges; const float* scale; int w = t;
        if (w < half) { edges = e1; scale = scl1; }
        else          { edges = e2; scale = scl2; w -= half; }
        int e    = w >> 4;
        int lane = w & 15;
        int s = __ldg(edges + e);          // broadcast within the 16-lane group
        int d = __ldg(edges + E + e);
        float4 v = __ldg(reinterpret_cast<const float4*>(feat) + ((size_t)d << 4) + lane);
        float sc = __ldg(scale + s);
        float* dst = agg + ((size_t)s << 6) + (lane << 2);
        red_add_v4(dst, v.x * sc, v.y * sc, v.z * sc, v.w * sc);
    }
}

// out = 0.25 * (base + l1 + l2 + l3)   (mean over the 4 layer snapshots)
__global__ void k_final3(const float4* __restrict__ base,
                         const float4* __restrict__ a,
                         const float4* __restrict__ b,
                         const float4* __restrict__ c,
                         float4* __restrict__ out, int n4) {
    int i = blockIdx.x * blockDim.x + threadIdx.x;
    if (i < n4) {
        float4 x = base[i], p = a[i], q = b[i], r = c[i];
        x.x = 0.25f * (x.x + p.x + q.x + r.x);
        x.y = 0.25f * (x.y + p.y + q.y + r.y);
        x.z = 0.25f * (x.z + p.z + q.z + r.z);
        x.w = 0.25f * (x.w + p.w + q.w + r.w);
        out[i] = x;
    }
}

// ---------------------------------------------------------------------------
// Launch (no statics, no caching — harness contract)
// ---------------------------------------------------------------------------
static inline int nblk(long long n, int t) { return (int)((n + t - 1) / t); }

extern "C" void kernel_launch(void* const* d_in, const int* in_sizes, int n_in,
                              void* d_out, int out_size) {
    const float* user_emb  = (const float*)d_in[0];
    const float* paper_emb = (const float*)d_in[1];
    const int*   er        = (const int*)d_in[2];
    const int*   ew        = (const int*)d_in[3];
    const int*   rr        = (const int*)d_in[4];
    const int*   rw        = (const int*)d_in[5];
    const int E = in_sizes[2] / 2;

    float* out = (float*)d_out;

    float *au[3], *ap[3];
    int *deg_er, *deg_ew, *deg_rr, *deg_rw;
    float *scl_er, *scl_ew, *scl_rr, *scl_rw;
    cudaGetSymbolAddress((void**)&au[0], g_au0);
    cudaGetSymbolAddress((void**)&au[1], g_au1);
    cudaGetSymbolAddress((void**)&au[2], g_au2);
    cudaGetSymbolAddress((void**)&ap[0], g_ap0);
    cudaGetSymbolAddress((void**)&ap[1], g_ap1);
    cudaGetSymbolAddress((void**)&ap[2], g_ap2);
    cudaGetSymbolAddress((void**)&deg_er, g_deg_er);
    cudaGetSymbolAddress((void**)&deg_ew, g_deg_ew);
    cudaGetSymbolAddress((void**)&deg_rr, g_deg_rr);
    cudaGetSymbolAddress((void**)&deg_rw, g_deg_rw);
    cudaGetSymbolAddress((void**)&scl_er, g_scl_er);
    cudaGetSymbolAddress((void**)&scl_ew, g_scl_ew);
    cudaGetSymbolAddress((void**)&scl_rr, g_scl_rr);
    cudaGetSymbolAddress((void**)&scl_rw, g_scl_rw);

    const int T = 256;
    const int UF4 = UF / 4, PF4 = PF / 4;
    const long long ST2 = (long long)E * 32;   // both lists, 16 threads/edge
    const int sgrid = nblk(ST2, T);

    // [1] zero au0 + all degree arrays (fused opener)
    k_zero_init<<<nblk(UF4, T), T>>>((float4*)au[0],
                                     deg_er, deg_ew, deg_rr, deg_rw, UF4);
    // [2] degrees
    k_deg4<<<nblk(E, T), T>>>(er, ew, rr, rw, E, deg_er, deg_ew, deg_rr, deg_rw);
    // [3] user scales
    k_scale2<<<nblk(NU, T), T>>>(deg_er, scl_er, deg_ew, scl_ew, NU);
    // [4] user scatter L0  <- ncu capture slot (lands on 4th launch)
    k_scatter2<<<sgrid, T>>>(er, scl_er, ew, scl_ew, E, paper_emb, au[0]);

    // [5] paper scales, [6] zero ap0, [7] paper scatter L0
    k_scale2<<<nblk(NP, T), T>>>(deg_rr, scl_rr, deg_rw, scl_rw, NP);
    k_zero_f4<<<nblk(PF4, T), T>>>((float4*)ap[0], PF4);
    k_scatter2<<<sgrid, T>>>(rr, scl_rr, rw, scl_rw, E, au[0], ap[0]);

    // layers 1..2
    for (int L = 1; L < 3; L++) {
        k_zero_f4<<<nblk(UF4, T), T>>>((float4*)au[L], UF4);
        k_scatter2<<<sgrid, T>>>(er, scl_er, ew, scl_ew, E, ap[L - 1], au[L]);
        k_zero_f4<<<nblk(PF4, T), T>>>((float4*)ap[L], PF4);
        k_scatter2<<<sgrid, T>>>(rr, scl_rr, rw, scl_rw, E, au[L], ap[L]);
    }

    // finalize: mean over {layer-0 emb, L1, L2, L3}; out = [u_final | p_final]
    k_final3<<<nblk(UF4, T), T>>>((const float4*)user_emb,
                                  (const float4*)au[0], (const float4*)au[1],
                                  (const float4*)au[2], (float4*)out, UF4);
    k_final3<<<nblk(PF4, T), T>>>((const float4*)paper_emb,
                                  (const float4*)ap[0], (const float4*)ap[1],
                                  (const float4*)ap[2],
                                  (float4*)(out + (size_t)UF), PF4);
}

// round 17
// speedup vs baseline: 1.4897x; 1.1983x over previous
#include <cuda_runtime.h>
#include <cstddef>

// Problem constants (match reference_code)
#define NU 500000
#define NP 100000
#define DIMF 64
#define UF (NU * DIMF)   // 32,000,000 floats (128 MB)
#define PF (NP * DIMF)   //  6,400,000 floats (25.6 MB)

// ---------------------------------------------------------------------------
// Scratch (static device globals — allocation-guard-safe). ~461 MB total.
// ---------------------------------------------------------------------------
__device__ float g_au0[UF];
__device__ float g_au1[UF];
__device__ float g_au2[UF];
__device__ float g_ap0[PF];
__device__ float g_ap1[PF];
__device__ float g_ap2[PF];

__device__ int   g_deg_er[NU], g_deg_ew[NU], g_deg_rr[NP], g_deg_rw[NP];
__device__ float g_scl_er[NU], g_scl_ew[NU], g_scl_rr[NP], g_scl_rw[NP];

// ---------------------------------------------------------------------------
// Vector f32 L2 reduction with scalar fallback.
// ---------------------------------------------------------------------------
__device__ __forceinline__ void red_add_v4(float* dst, float a, float b, float c, float d) {
#if defined(__CUDA_ARCH__) && (__CUDA_ARCH__ >= 900)
    asm volatile("red.global.add.v4.f32 [%0], {%1,%2,%3,%4};"
                 :: "l"(dst), "f"(a), "f"(b), "f"(c), "f"(d) : "memory");
#else
    atomicAdd(dst + 0, a); atomicAdd(dst + 1, b);
    atomicAdd(dst + 2, c); atomicAdd(dst + 3, d);
#endif
}

// ---------------------------------------------------------------------------
// Kernels
// ---------------------------------------------------------------------------
// Opening kernel: zero au0 + all four degree arrays in one launch,
// so the first big scatter sits at launch index 4 (ncu capture slot).
__global__ void k_zero_init(float4* __restrict__ au0,
                            int* __restrict__ du0, int* __restrict__ du1,
                            int* __restrict__ dp0, int* __restrict__ dp1,
                            int n4) {
    int i = blockIdx.x * blockDim.x + threadIdx.x;
    if (i < n4) au0[i] = make_float4(0.f, 0.f, 0.f, 0.f);
    if (i < NU) { du0[i] = 0; du1[i] = 0; }
    if (i < NP) { dp0[i] = 0; dp1[i] = 0; }
}

__global__ void k_zero_f4(float4* __restrict__ p, int n4) {
    int i = blockIdx.x * blockDim.x + threadIdx.x;
    if (i < n4) p[i] = make_float4(0.f, 0.f, 0.f, 0.f);
}

// All four degree histograms in one launch.
__global__ void k_deg4(const int* __restrict__ er, const int* __restrict__ ew,
                       const int* __restrict__ rr, const int* __restrict__ rw, int E,
                       int* __restrict__ der, int* __restrict__ dew,
                       int* __restrict__ drr, int* __restrict__ drw) {
    int i = blockIdx.x * blockDim.x + threadIdx.x;
    if (i >= E) return;
    atomicAdd(&der[er[i]], 1);
    atomicAdd(&dew[ew[i]], 1);
    atomicAdd(&drr[rr[i]], 1);
    atomicAdd(&drw[rw[i]], 1);
}

// scale = 0.5 / max(deg, 1): folds degree-normalization AND the (r+w)/2 avg.
__global__ void k_scale2(const int* __restrict__ da, float* __restrict__ sa,
                         const int* __restrict__ db, float* __restrict__ sb, int n) {
    int i = blockIdx.x * blockDim.x + threadIdx.x;
    if (i < n) {
        int a = da[i], b = db[i];
        sa[i] = 0.5f / (float)(a > 1 ? a : 1);
        sb[i] = 0.5f / (float)(b > 1 ? b : 1);
    }
}

// Fused dual-edge-list scatter, MLP=4 version:
//   4 lanes per edge; each thread loads indices ONCE, then issues
//   4 independent float4 gathers + 4 independent v4 REDs (row = 16 float4s,
//   lane handles float4s {lane, lane+4, lane+8, lane+12}).
// List boundary at E*4 threads is warp-aligned (E multiple of 8).
__global__ void __launch_bounds__(256, 6)
k_scatter2(const int* __restrict__ e1, const float* __restrict__ scl1,
           const int* __restrict__ e2, const float* __restrict__ scl2,
           int E,
           const float* __restrict__ feat,
           float* __restrict__ agg) {
    int t = blockIdx.x * blockDim.x + threadIdx.x;
    const int half  = E * 4;
    const int total = half * 2;
    if (t >= total) return;
    const int* edges; const float* scale;
    if (t < half) { edges = e1; scale = scl1; }
    else          { edges = e2; scale = scl2; t -= half; }
    int e    = t >> 2;
    int lane = t & 3;
    int s = __ldg(edges + e);
    int d = __ldg(edges + E + e);
    float sc = __ldg(scale + s);
    const float4* row = reinterpret_cast<const float4*>(feat) + ((size_t)d << 4);
    // 4 independent gathers (two 128B lines of the 256B row, interleaved)
    float4 v0 = __ldg(row + lane);
    float4 v1 = __ldg(row + lane + 4);
    float4 v2 = __ldg(row + lane + 8);
    float4 v3 = __ldg(row + lane + 12);
    float* dst = agg + ((size_t)s << 6);
    red_add_v4(dst + (lane << 2),        v0.x * sc, v0.y * sc, v0.z * sc, v0.w * sc);
    red_add_v4(dst + ((lane + 4) << 2),  v1.x * sc, v1.y * sc, v1.z * sc, v1.w * sc);
    red_add_v4(dst + ((lane + 8) << 2),  v2.x * sc, v2.y * sc, v2.z * sc, v2.w * sc);
    red_add_v4(dst + ((lane + 12) << 2), v3.x * sc, v3.y * sc, v3.z * sc, v3.w * sc);
}

// out = 0.25 * (base + l1 + l2 + l3)   (mean over the 4 layer snapshots)
__global__ void k_final3(const float4* __restrict__ base,
                         const float4* __restrict__ a,
                         const float4* __restrict__ b,
                         const float4* __restrict__ c,
                         float4* __restrict__ out, int n4) {
    int i = blockIdx.x * blockDim.x + threadIdx.x;
    if (i < n4) {
        float4 x = base[i], p = a[i], q = b[i], r = c[i];
        x.x = 0.25f * (x.x + p.x + q.x + r.x);
        x.y = 0.25f * (x.y + p.y + q.y + r.y);
        x.z = 0.25f * (x.z + p.z + q.z + r.z);
        x.w = 0.25f * (x.w + p.w + q.w + r.w);
        out[i] = x;
    }
}

// ---------------------------------------------------------------------------
// Launch (no statics, no caching — harness contract)
// ---------------------------------------------------------------------------
static inline int nblk(long long n, int t) { return (int)((n + t - 1) / t); }

extern "C" void kernel_launch(void* const* d_in, const int* in_sizes, int n_in,
                              void* d_out, int out_size) {
    const float* user_emb  = (const float*)d_in[0];
    const float* paper_emb = (const float*)d_in[1];
    const int*   er        = (const int*)d_in[2];
    const int*   ew        = (const int*)d_in[3];
    const int*   rr        = (const int*)d_in[4];
    const int*   rw        = (const int*)d_in[5];
    const int E = in_sizes[2] / 2;

    float* out = (float*)d_out;

    float *au[3], *ap[3];
    int *deg_er, *deg_ew, *deg_rr, *deg_rw;
    float *scl_er, *scl_ew, *scl_rr, *scl_rw;
    cudaGetSymbolAddress((void**)&au[0], g_au0);
    cudaGetSymbolAddress((void**)&au[1], g_au1);
    cudaGetSymbolAddress((void**)&au[2], g_au2);
    cudaGetSymbolAddress((void**)&ap[0], g_ap0);
    cudaGetSymbolAddress((void**)&ap[1], g_ap1);
    cudaGetSymbolAddress((void**)&ap[2], g_ap2);
    cudaGetSymbolAddress((void**)&deg_er, g_deg_er);
    cudaGetSymbolAddress((void**)&deg_ew, g_deg_ew);
    cudaGetSymbolAddress((void**)&deg_rr, g_deg_rr);
    cudaGetSymbolAddress((void**)&deg_rw, g_deg_rw);
    cudaGetSymbolAddress((void**)&scl_er, g_scl_er);
    cudaGetSymbolAddress((void**)&scl_ew, g_scl_ew);
    cudaGetSymbolAddress((void**)&scl_rr, g_scl_rr);
    cudaGetSymbolAddress((void**)&scl_rw, g_scl_rw);

    const int T = 256;
    const int UF4 = UF / 4, PF4 = PF / 4;
    const long long ST2 = (long long)E * 8;    // both lists, 4 threads/edge
    const int sgrid = nblk(ST2, T);

    // [1] zero au0 + all degree arrays (fused opener)
    k_zero_init<<<nblk(UF4, T), T>>>((float4*)au[0],
                                     deg_er, deg_ew, deg_rr, deg_rw, UF4);
    // [2] degrees
    k_deg4<<<nblk(E, T), T>>>(er, ew, rr, rw, E, deg_er, deg_ew, deg_rr, deg_rw);
    // [3] user scales
    k_scale2<<<nblk(NU, T), T>>>(deg_er, scl_er, deg_ew, scl_ew, NU);
    // [4] user scatter L0  <- ncu capture slot
    k_scatter2<<<sgrid, T>>>(er, scl_er, ew, scl_ew, E, paper_emb, au[0]);

    // [5] paper scales, [6] zero ap0, [7] paper scatter L0
    k_scale2<<<nblk(NP, T), T>>>(deg_rr, scl_rr, deg_rw, scl_rw, NP);
    k_zero_f4<<<nblk(PF4, T), T>>>((float4*)ap[0], PF4);
    k_scatter2<<<sgrid, T>>>(rr, scl_rr, rw, scl_rw, E, au[0], ap[0]);

    // layers 1..2
    for (int L = 1; L < 3; L++) {
        k_zero_f4<<<nblk(UF4, T), T>>>((float4*)au[L], UF4);
        k_scatter2<<<sgrid, T>>>(er, scl_er, ew, scl_ew, E, ap[L - 1], au[L]);
        k_zero_f4<<<nblk(PF4, T), T>>>((float4*)ap[L], PF4);
        k_scatter2<<<sgrid, T>>>(rr, scl_rr, rw, scl_rw, E, au[L], ap[L]);
    }

    // finalize: mean over {layer-0 emb, L1, L2, L3}; out = [u_final | p_final]
    k_final3<<<nblk(UF4, T), T>>>((const float4*)user_emb,
                                  (const float4*)au[0], (const float4*)au[1],
                                  (const float4*)au[2], (float4*)out, UF4);
    k_final3<<<nblk(PF4, T), T>>>((const float4*)paper_emb,
                                  (const float4*)ap[0], (const float4*)ap[1],
                                  (const float4*)ap[2],
                                  (float4*)(out + (size_t)UF), PF4);
}